// round 1
// baseline (speedup 1.0000x reference)
#include <cuda_runtime.h>
#include <cuda_fp16.h>
#include <cstdint>

#define B_ 4
#define L_ 4096
#define H_ 16
#define DH_ 128
#define DV_ 128
#define CHUNK_ 1024
#define NC_ (L_/CHUNK_)

// fp16 scratch, head-major [B][H][L][128]
__device__ __half g_q[(size_t)B_*H_*L_*DH_];
__device__ __half g_k[(size_t)B_*H_*L_*DH_];
__device__ __half g_v[(size_t)B_*H_*L_*DV_];

// ---------------------------------------------------------------------------
// Kernel 1: RoPE + scale-fold + fp32->fp16 convert, relayout to head-major
// ---------------------------------------------------------------------------
__global__ void rope_cvt_kernel(const float* __restrict__ q,
                                const float* __restrict__ k,
                                const float* __restrict__ v) {
    // 4 rows (b,t,h) per block of 256; 64 threads per row (one per freq f)
    int gid = blockIdx.x * 4 + (threadIdx.x >> 6);   // row in [0, B*L*H)
    int f   = threadIdx.x & 63;
    int h = gid % H_;
    int bt = gid / H_;
    int t = bt % L_;
    int b = bt / L_;

    size_t in_base  = (size_t)gid * 128;                       // (B,L,H,D)
    size_t out_base = (((size_t)(b*H_ + h))*L_ + t) * 128;     // (B,H,L,D)

    // inv_freq = exp(f * -ln(10000)/64)
    float inv = expf((float)f * (-9.210340371976184f / 64.0f));
    float ang = (float)t * inv;
    float s, c;
    sincosf(ang, &s, &c);

    const float sc = 0.08838834764831845f; // 1/sqrt(128), folded into Q

    float q1 = q[in_base + f], q2 = q[in_base + f + 64];
    float k1 = k[in_base + f], k2 = k[in_base + f + 64];

    g_q[out_base + f]      = __float2half_rn((q1*c - q2*s) * sc);
    g_q[out_base + f + 64] = __float2half_rn((q1*s + q2*c) * sc);
    g_k[out_base + f]      = __float2half_rn(k1*c - k2*s);
    g_k[out_base + f + 64] = __float2half_rn(k1*s + k2*c);
    g_v[out_base + f]      = __float2half_rn(v[in_base + f]);
    g_v[out_base + f + 64] = __float2half_rn(v[in_base + f + 64]);
}

// ---------------------------------------------------------------------------
// mma.sync + ldmatrix helpers
// ---------------------------------------------------------------------------
__device__ __forceinline__ uint32_t smem_u32(const void* p) {
    return (uint32_t)__cvta_generic_to_shared(p);
}

__device__ __forceinline__ void ldsm_x4(uint32_t& a0, uint32_t& a1,
                                        uint32_t& a2, uint32_t& a3, uint32_t addr) {
    asm volatile("ldmatrix.sync.aligned.m8n8.x4.shared.b16 {%0,%1,%2,%3}, [%4];\n"
                 : "=r"(a0), "=r"(a1), "=r"(a2), "=r"(a3) : "r"(addr));
}
__device__ __forceinline__ void ldsm_x2(uint32_t& a0, uint32_t& a1, uint32_t addr) {
    asm volatile("ldmatrix.sync.aligned.m8n8.x2.shared.b16 {%0,%1}, [%2];\n"
                 : "=r"(a0), "=r"(a1) : "r"(addr));
}
__device__ __forceinline__ void ldsm_x2_t(uint32_t& a0, uint32_t& a1, uint32_t addr) {
    asm volatile("ldmatrix.sync.aligned.m8n8.x2.trans.shared.b16 {%0,%1}, [%2];\n"
                 : "=r"(a0), "=r"(a1) : "r"(addr));
}
__device__ __forceinline__ void mma16816(float* d, const uint32_t* a, const uint32_t* b) {
    asm volatile(
        "mma.sync.aligned.m16n8k16.row.col.f32.f16.f16.f32 "
        "{%0,%1,%2,%3},{%4,%5,%6,%7},{%8,%9},{%0,%1,%2,%3};\n"
        : "+f"(d[0]), "+f"(d[1]), "+f"(d[2]), "+f"(d[3])
        : "r"(a[0]), "r"(a[1]), "r"(a[2]), "r"(a[3]), "r"(b[0]), "r"(b[1]));
}
__device__ __forceinline__ uint32_t pack_h2(float lo, float hi) {
    __half2 h = __floats2half2_rn(lo, hi);
    return *reinterpret_cast<uint32_t*>(&h);
}

// ---------------------------------------------------------------------------
// Kernel 2: flash attention within 1024-chunks, causal
// CTA: 8 warps, BM=128 rows (16 per warp), BN=64 cols per K tile
// ---------------------------------------------------------------------------
#define SQ_STRIDE 136   // 128 + 8 halves pad (272B rows -> conflict-free ldmatrix)

__global__ __launch_bounds__(256, 1)
void flash_kernel(float* __restrict__ out) {
    extern __shared__ __half smem[];
    __half* Qs = smem;                         // 128 x 136
    __half* Ks = smem + 128 * SQ_STRIDE;       //  64 x 136
    __half* Vs = Ks + 64 * SQ_STRIDE;          //  64 x 136

    const int mtile = blockIdx.x;              // 0..7
    const int h     = blockIdx.y;              // 0..15
    const int bn    = blockIdx.z;              // 0..15
    const int b = bn / NC_, n = bn % NC_;
    const int m0 = mtile * 128;

    const int tid  = threadIdx.x;
    const int warp = tid >> 5;
    const int lane = tid & 31;

    const size_t headbase = ((size_t)(b*H_ + h)) * L_ * 128 + (size_t)n * CHUNK_ * 128;

    // ---- load Q tile (128x128) into smem, vectorized ----
    {
        const __half* Qg = g_q + headbase + (size_t)m0 * 128;
        #pragma unroll
        for (int i = tid; i < 128 * 16; i += 256) {
            int r = i >> 4, s = i & 15;
            *(uint4*)(Qs + r * SQ_STRIDE + s * 8) = *(const uint4*)(Qg + r * 128 + s * 8);
        }
    }
    __syncthreads();

    // ---- Q fragments resident in registers for the whole K loop ----
    const uint32_t sQ = smem_u32(Qs);
    const uint32_t sK = smem_u32(Ks);
    const uint32_t sV = smem_u32(Vs);
    uint32_t qa[8][4];
    {
        int row = warp * 16 + (lane & 15);
        int col8 = (lane >> 4) << 3;
        #pragma unroll
        for (int kk = 0; kk < 8; kk++) {
            uint32_t addr = sQ + (uint32_t)((row * SQ_STRIDE + kk * 16 + col8) * 2);
            ldsm_x4(qa[kk][0], qa[kk][1], qa[kk][2], qa[kk][3], addr);
        }
    }

    // ---- online-softmax state ----
    float of[16][4];
    #pragma unroll
    for (int i = 0; i < 16; i++)
        #pragma unroll
        for (int j = 0; j < 4; j++) of[i][j] = 0.f;
    float m_r0 = -1e30f, m_r1 = -1e30f;
    float l_r0 = 0.f,    l_r1 = 0.f;

    const int ktiles = 2 * mtile + 2;

    for (int kt = 0; kt < ktiles; kt++) {
        // load K/V tile (64x128 each)
        __syncthreads();  // previous iteration's smem reads done
        {
            const __half* Kg = g_k + headbase + (size_t)kt * 64 * 128;
            const __half* Vg = g_v + headbase + (size_t)kt * 64 * 128;
            #pragma unroll
            for (int i = tid; i < 64 * 16; i += 256) {
                int r = i >> 4, s = i & 15;
                *(uint4*)(Ks + r * SQ_STRIDE + s * 8) = *(const uint4*)(Kg + r * 128 + s * 8);
                *(uint4*)(Vs + r * SQ_STRIDE + s * 8) = *(const uint4*)(Vg + r * 128 + s * 8);
            }
        }
        __syncthreads();

        // ---- S = Q K^T  (16 x 64 per warp) ----
        float sf[8][4];
        #pragma unroll
        for (int i = 0; i < 8; i++)
            #pragma unroll
            for (int j = 0; j < 4; j++) sf[i][j] = 0.f;

        {
            int krow = lane & 7;
            int kcol8 = ((lane >> 3) & 1) << 3;
            #pragma unroll
            for (int kk = 0; kk < 8; kk++) {
                #pragma unroll
                for (int nt = 0; nt < 8; nt++) {
                    uint32_t bfr[2];
                    uint32_t addr = sK + (uint32_t)((((nt * 8 + krow) * SQ_STRIDE)
                                     + kk * 16 + kcol8) * 2);
                    ldsm_x2(bfr[0], bfr[1], addr);
                    mma16816(sf[nt], qa[kk], bfr);
                }
            }
        }

        // ---- causal mask (only the two diagonal-region tiles need it) ----
        if (kt >= 2 * mtile) {
            int r0 = m0 + warp * 16 + (lane >> 2);
            int cbase = kt * 64 + ((lane & 3) << 1);
            #pragma unroll
            for (int nt = 0; nt < 8; nt++) {
                int c0 = cbase + nt * 8;
                if (c0     > r0)     sf[nt][0] = -1e30f;
                if (c0 + 1 > r0)     sf[nt][1] = -1e30f;
                if (c0     > r0 + 8) sf[nt][2] = -1e30f;
                if (c0 + 1 > r0 + 8) sf[nt][3] = -1e30f;
            }
        }

        // ---- online softmax update ----
        float rmax0 = -1e30f, rmax1 = -1e30f;
        #pragma unroll
        for (int nt = 0; nt < 8; nt++) {
            rmax0 = fmaxf(rmax0, fmaxf(sf[nt][0], sf[nt][1]));
            rmax1 = fmaxf(rmax1, fmaxf(sf[nt][2], sf[nt][3]));
        }
        rmax0 = fmaxf(rmax0, __shfl_xor_sync(0xffffffffu, rmax0, 1));
        rmax0 = fmaxf(rmax0, __shfl_xor_sync(0xffffffffu, rmax0, 2));
        rmax1 = fmaxf(rmax1, __shfl_xor_sync(0xffffffffu, rmax1, 1));
        rmax1 = fmaxf(rmax1, __shfl_xor_sync(0xffffffffu, rmax1, 2));

        float nm0 = fmaxf(m_r0, rmax0);
        float nm1 = fmaxf(m_r1, rmax1);
        float sc0 = __expf(m_r0 - nm0);
        float sc1 = __expf(m_r1 - nm1);

        float rs0 = 0.f, rs1 = 0.f;
        #pragma unroll
        for (int nt = 0; nt < 8; nt++) {
            sf[nt][0] = __expf(sf[nt][0] - nm0);
            sf[nt][1] = __expf(sf[nt][1] - nm0);
            sf[nt][2] = __expf(sf[nt][2] - nm1);
            sf[nt][3] = __expf(sf[nt][3] - nm1);
            rs0 += sf[nt][0] + sf[nt][1];
            rs1 += sf[nt][2] + sf[nt][3];
        }
        rs0 += __shfl_xor_sync(0xffffffffu, rs0, 1);
        rs0 += __shfl_xor_sync(0xffffffffu, rs0, 2);
        rs1 += __shfl_xor_sync(0xffffffffu, rs1, 1);
        rs1 += __shfl_xor_sync(0xffffffffu, rs1, 2);

        l_r0 = l_r0 * sc0 + rs0;
        l_r1 = l_r1 * sc1 + rs1;
        m_r0 = nm0;
        m_r1 = nm1;

        #pragma unroll
        for (int nt = 0; nt < 16; nt++) {
            of[nt][0] *= sc0; of[nt][1] *= sc0;
            of[nt][2] *= sc1; of[nt][3] *= sc1;
        }

        // ---- O += P V  (P stays in registers: C-frag layout == A-frag layout) ----
        {
            int vrow = lane & 15;
            #pragma unroll
            for (int kt2 = 0; kt2 < 4; kt2++) {
                uint32_t pa[4];
                pa[0] = pack_h2(sf[2*kt2][0],   sf[2*kt2][1]);
                pa[1] = pack_h2(sf[2*kt2][2],   sf[2*kt2][3]);
                pa[2] = pack_h2(sf[2*kt2+1][0], sf[2*kt2+1][1]);
                pa[3] = pack_h2(sf[2*kt2+1][2], sf[2*kt2+1][3]);
                #pragma unroll
                for (int nt = 0; nt < 16; nt++) {
                    uint32_t bfr[2];
                    uint32_t addr = sV + (uint32_t)((((kt2 * 16 + vrow) * SQ_STRIDE)
                                     + nt * 8) * 2);
                    ldsm_x2_t(bfr[0], bfr[1], addr);
                    mma16816(of[nt], pa, bfr);
                }
            }
        }
    }

    // ---- epilogue: normalize and write out (B, L, H*DV) fp32 ----
    float inv0 = 1.f / l_r0;
    float inv1 = 1.f / l_r1;
    int row0 = n * CHUNK_ + m0 + warp * 16 + (lane >> 2);
    int colb = h * 128 + ((lane & 3) << 1);
    size_t ob0 = ((size_t)b * L_ + row0) * (size_t)(H_ * DV_);
    size_t ob1 = ob0 + (size_t)8 * (H_ * DV_);
    #pragma unroll
    for (int nt = 0; nt < 16; nt++) {
        int c = colb + nt * 8;
        float2 v0 = make_float2(of[nt][0] * inv0, of[nt][1] * inv0);
        float2 v1 = make_float2(of[nt][2] * inv1, of[nt][3] * inv1);
        *(float2*)(out + ob0 + c) = v0;
        *(float2*)(out + ob1 + c) = v1;
    }
}

// ---------------------------------------------------------------------------
extern "C" void kernel_launch(void* const* d_in, const int* in_sizes, int n_in,
                              void* d_out, int out_size) {
    const float* q = (const float*)d_in[0];
    const float* k = (const float*)d_in[1];
    const float* v = (const float*)d_in[2];
    float* out = (float*)d_out;

    const int smem_bytes = (128 * SQ_STRIDE + 2 * 64 * SQ_STRIDE) * (int)sizeof(__half);
    cudaFuncSetAttribute(flash_kernel,
                         cudaFuncAttributeMaxDynamicSharedMemorySize, smem_bytes);

    rope_cvt_kernel<<<(B_ * L_ * H_) / 4, 256>>>(q, k, v);
    flash_kernel<<<dim3(8, H_, B_ * NC_), 256, smem_bytes>>>(out);
}

// round 2
// speedup vs baseline: 1.1637x; 1.1637x over previous
#include <cuda_runtime.h>
#include <cuda_fp16.h>
#include <cstdint>

#define B_ 4
#define L_ 4096
#define H_ 16
#define DH_ 128
#define DV_ 128
#define CHUNK_ 1024
#define NC_ (L_/CHUNK_)

// fp16 scratch, head-major [B][H][L][128]
__device__ __half g_q[(size_t)B_*H_*L_*DH_];
__device__ __half g_k[(size_t)B_*H_*L_*DH_];
__device__ __half g_v[(size_t)B_*H_*L_*DV_];

// ---------------------------------------------------------------------------
// Kernel 1: RoPE + scale-fold (1/sqrt(128) * log2e into Q) + fp32->fp16,
// relayout to head-major
// ---------------------------------------------------------------------------
__global__ void rope_cvt_kernel(const float* __restrict__ q,
                                const float* __restrict__ k,
                                const float* __restrict__ v) {
    int gid = blockIdx.x * 4 + (threadIdx.x >> 6);   // row in [0, B*L*H)
    int f   = threadIdx.x & 63;
    int h = gid % H_;
    int bt = gid / H_;
    int t = bt % L_;
    int b = bt / L_;

    size_t in_base  = (size_t)gid * 128;                       // (B,L,H,D)
    size_t out_base = (((size_t)(b*H_ + h))*L_ + t) * 128;     // (B,H,L,D)

    float inv = expf((float)f * (-9.210340371976184f / 64.0f));
    float ang = (float)t * inv;
    float s, c;
    sincosf(ang, &s, &c);

    // 1/sqrt(128) * log2(e): softmax done in base-2 domain downstream
    const float sc = 0.08838834764831845f * 1.4426950408889634f;

    float q1 = q[in_base + f], q2 = q[in_base + f + 64];
    float k1 = k[in_base + f], k2 = k[in_base + f + 64];

    g_q[out_base + f]      = __float2half_rn((q1*c - q2*s) * sc);
    g_q[out_base + f + 64] = __float2half_rn((q1*s + q2*c) * sc);
    g_k[out_base + f]      = __float2half_rn(k1*c - k2*s);
    g_k[out_base + f + 64] = __float2half_rn(k1*s + k2*c);
    g_v[out_base + f]      = __float2half_rn(v[in_base + f]);
    g_v[out_base + f + 64] = __float2half_rn(v[in_base + f + 64]);
}

// ---------------------------------------------------------------------------
// PTX helpers
// ---------------------------------------------------------------------------
__device__ __forceinline__ uint32_t smem_u32(const void* p) {
    return (uint32_t)__cvta_generic_to_shared(p);
}
__device__ __forceinline__ void ldsm_x4(uint32_t& a0, uint32_t& a1,
                                        uint32_t& a2, uint32_t& a3, uint32_t addr) {
    asm volatile("ldmatrix.sync.aligned.m8n8.x4.shared.b16 {%0,%1,%2,%3}, [%4];\n"
                 : "=r"(a0), "=r"(a1), "=r"(a2), "=r"(a3) : "r"(addr));
}
__device__ __forceinline__ void ldsm_x4_t(uint32_t& a0, uint32_t& a1,
                                          uint32_t& a2, uint32_t& a3, uint32_t addr) {
    asm volatile("ldmatrix.sync.aligned.m8n8.x4.trans.shared.b16 {%0,%1,%2,%3}, [%4];\n"
                 : "=r"(a0), "=r"(a1), "=r"(a2), "=r"(a3) : "r"(addr));
}
__device__ __forceinline__ void mma16816(float* d, const uint32_t* a, const uint32_t* b) {
    asm volatile(
        "mma.sync.aligned.m16n8k16.row.col.f32.f16.f16.f32 "
        "{%0,%1,%2,%3},{%4,%5,%6,%7},{%8,%9},{%0,%1,%2,%3};\n"
        : "+f"(d[0]), "+f"(d[1]), "+f"(d[2]), "+f"(d[3])
        : "r"(a[0]), "r"(a[1]), "r"(a[2]), "r"(a[3]), "r"(b[0]), "r"(b[1]));
}
__device__ __forceinline__ uint32_t pack_h2(float lo, float hi) {
    __half2 h = __floats2half2_rn(lo, hi);
    return *reinterpret_cast<uint32_t*>(&h);
}
__device__ __forceinline__ float fexp2(float x) {
    float r;
    asm("ex2.approx.f32 %0, %1;" : "=f"(r) : "f"(x));
    return r;
}
__device__ __forceinline__ void cpa16(uint32_t dst, const void* src) {
    asm volatile("cp.async.cg.shared.global [%0], [%1], 16;\n"
                 :: "r"(dst), "l"(src));
}
__device__ __forceinline__ void cpa_commit() {
    asm volatile("cp.async.commit_group;\n");
}
__device__ __forceinline__ void cpa_wait0() {
    asm volatile("cp.async.wait_group 0;\n");
}

// ---------------------------------------------------------------------------
// Kernel 2: flash attention in 1024-chunks, causal.
// CTA: 8 warps, BM=128 rows (16/warp), BN=64, 2-stage cp.async pipeline.
// ---------------------------------------------------------------------------
#define SQ_STRIDE 136   // 128 + 8 halves pad; 272B rows (16B-aligned, conflict-free)

__global__ __launch_bounds__(256, 1)
void flash_kernel(float* __restrict__ out) {
    extern __shared__ __half smem[];
    __half* Qs = smem;                          // 128 x 136
    __half* Ks = smem + 128 * SQ_STRIDE;        // 2 x (64 x 136)
    __half* Vs = Ks + 2 * 64 * SQ_STRIDE;       // 2 x (64 x 136)

    const int mtile = 7 - blockIdx.x;           // long CTAs first
    const int h     = blockIdx.y;
    const int bn    = blockIdx.z;
    const int b = bn / NC_, n = bn % NC_;
    const int m0 = mtile * 128;

    const int tid  = threadIdx.x;
    const int warp = tid >> 5;
    const int lane = tid & 31;

    const size_t headbase = ((size_t)(b*H_ + h)) * L_ * 128 + (size_t)n * CHUNK_ * 128;
    const __half* Kg = g_k + headbase;
    const __half* Vg = g_v + headbase;

    const uint32_t sQ = smem_u32(Qs);
    const uint32_t sK = smem_u32(Ks);
    const uint32_t sV = smem_u32(Vs);

    const int ktiles = 2 * mtile + 2;

    // ---- prologue: async-load Q tile + K/V tile 0 ----
    {
        const __half* Qg = g_q + headbase + (size_t)m0 * 128;
        #pragma unroll
        for (int i = tid; i < 128 * 16; i += 256) {
            int r = i >> 4, s = i & 15;
            cpa16(sQ + (uint32_t)((r * SQ_STRIDE + s * 8) * 2), Qg + r * 128 + s * 8);
        }
        #pragma unroll
        for (int i = tid; i < 64 * 16; i += 256) {
            int r = i >> 4, s = i & 15;
            uint32_t off = (uint32_t)((r * SQ_STRIDE + s * 8) * 2);
            cpa16(sK + off, Kg + r * 128 + s * 8);
            cpa16(sV + off, Vg + r * 128 + s * 8);
        }
        cpa_commit();
    }
    cpa_wait0();
    __syncthreads();

    // ---- Q fragments register-resident for whole K loop ----
    uint32_t qa[8][4];
    {
        int row = warp * 16 + (lane & 15);
        int col8 = (lane >> 4) << 3;
        #pragma unroll
        for (int kk = 0; kk < 8; kk++) {
            uint32_t addr = sQ + (uint32_t)((row * SQ_STRIDE + kk * 16 + col8) * 2);
            ldsm_x4(qa[kk][0], qa[kk][1], qa[kk][2], qa[kk][3], addr);
        }
    }

    // per-lane ldmatrix address parts
    const int kmat  = lane >> 3;                        // 0..3
    const int kRow  = ((kmat >> 1) << 3) + (lane & 7);  // row-within-(2x8)-pair
    const int kCol  = (kmat & 1) << 3;                  // 0 or 8
    const int vRow  = lane & 15;
    const int vSel  = lane >> 4;                        // 0/1 -> nt, nt+1

    // ---- online-softmax state ----
    float of[16][4];
    #pragma unroll
    for (int i = 0; i < 16; i++)
        #pragma unroll
        for (int j = 0; j < 4; j++) of[i][j] = 0.f;
    float m_r0 = -1e30f, m_r1 = -1e30f;
    float l_r0 = 0.f,    l_r1 = 0.f;

    for (int kt = 0; kt < ktiles; kt++) {
        const uint32_t sKb = sK + (uint32_t)((kt & 1) * 64 * SQ_STRIDE * 2);
        const uint32_t sVb = sV + (uint32_t)((kt & 1) * 64 * SQ_STRIDE * 2);

        // issue next tile's loads into the other buffer (overlaps with compute)
        if (kt + 1 < ktiles) {
            const __half* Kn = Kg + (size_t)(kt + 1) * 64 * 128;
            const __half* Vn = Vg + (size_t)(kt + 1) * 64 * 128;
            uint32_t sKn = sK + (uint32_t)(((kt + 1) & 1) * 64 * SQ_STRIDE * 2);
            uint32_t sVn = sV + (uint32_t)(((kt + 1) & 1) * 64 * SQ_STRIDE * 2);
            #pragma unroll
            for (int i = tid; i < 64 * 16; i += 256) {
                int r = i >> 4, s = i & 15;
                uint32_t off = (uint32_t)((r * SQ_STRIDE + s * 8) * 2);
                cpa16(sKn + off, Kn + r * 128 + s * 8);
                cpa16(sVn + off, Vn + r * 128 + s * 8);
            }
            cpa_commit();
        }

        // ---- S = Q K^T (16 x 64 per warp) ----
        float sf[8][4];
        #pragma unroll
        for (int i = 0; i < 8; i++)
            #pragma unroll
            for (int j = 0; j < 4; j++) sf[i][j] = 0.f;

        #pragma unroll
        for (int kk = 0; kk < 8; kk++) {
            #pragma unroll
            for (int nt = 0; nt < 8; nt += 2) {
                uint32_t b4[4];
                uint32_t addr = sKb + (uint32_t)((((nt * 8 + kRow) * SQ_STRIDE)
                                 + kk * 16 + kCol) * 2);
                ldsm_x4(b4[0], b4[1], b4[2], b4[3], addr);
                mma16816(sf[nt],     qa[kk], b4);
                mma16816(sf[nt + 1], qa[kk], b4 + 2);
            }
        }

        // ---- causal mask (diagonal-region tiles only) ----
        if (kt >= 2 * mtile) {
            int r0 = m0 + warp * 16 + (lane >> 2);
            int cbase = kt * 64 + ((lane & 3) << 1);
            #pragma unroll
            for (int nt = 0; nt < 8; nt++) {
                int c0 = cbase + nt * 8;
                if (c0     > r0)     sf[nt][0] = -1e30f;
                if (c0 + 1 > r0)     sf[nt][1] = -1e30f;
                if (c0     > r0 + 8) sf[nt][2] = -1e30f;
                if (c0 + 1 > r0 + 8) sf[nt][3] = -1e30f;
            }
        }

        // ---- online softmax (base-2 domain; log2e pre-folded into Q) ----
        float rmax0 = -1e30f, rmax1 = -1e30f;
        #pragma unroll
        for (int nt = 0; nt < 8; nt++) {
            rmax0 = fmaxf(rmax0, fmaxf(sf[nt][0], sf[nt][1]));
            rmax1 = fmaxf(rmax1, fmaxf(sf[nt][2], sf[nt][3]));
        }
        rmax0 = fmaxf(rmax0, __shfl_xor_sync(0xffffffffu, rmax0, 1));
        rmax0 = fmaxf(rmax0, __shfl_xor_sync(0xffffffffu, rmax0, 2));
        rmax1 = fmaxf(rmax1, __shfl_xor_sync(0xffffffffu, rmax1, 1));
        rmax1 = fmaxf(rmax1, __shfl_xor_sync(0xffffffffu, rmax1, 2));

        float nm0 = fmaxf(m_r0, rmax0);
        float nm1 = fmaxf(m_r1, rmax1);
        float sc0 = fexp2(m_r0 - nm0);
        float sc1 = fexp2(m_r1 - nm1);

        float rs0 = 0.f, rs1 = 0.f;
        #pragma unroll
        for (int nt = 0; nt < 8; nt++) {
            sf[nt][0] = fexp2(sf[nt][0] - nm0);
            sf[nt][1] = fexp2(sf[nt][1] - nm0);
            sf[nt][2] = fexp2(sf[nt][2] - nm1);
            sf[nt][3] = fexp2(sf[nt][3] - nm1);
            rs0 += sf[nt][0] + sf[nt][1];
            rs1 += sf[nt][2] + sf[nt][3];
        }
        rs0 += __shfl_xor_sync(0xffffffffu, rs0, 1);
        rs0 += __shfl_xor_sync(0xffffffffu, rs0, 2);
        rs1 += __shfl_xor_sync(0xffffffffu, rs1, 1);
        rs1 += __shfl_xor_sync(0xffffffffu, rs1, 2);

        l_r0 = l_r0 * sc0 + rs0;
        l_r1 = l_r1 * sc1 + rs1;
        m_r0 = nm0;
        m_r1 = nm1;

        #pragma unroll
        for (int nt = 0; nt < 16; nt++) {
            of[nt][0] *= sc0; of[nt][1] *= sc0;
            of[nt][2] *= sc1; of[nt][3] *= sc1;
        }

        // ---- O += P V ----
        #pragma unroll
        for (int kt2 = 0; kt2 < 4; kt2++) {
            uint32_t pa[4];
            pa[0] = pack_h2(sf[2*kt2][0],   sf[2*kt2][1]);
            pa[1] = pack_h2(sf[2*kt2][2],   sf[2*kt2][3]);
            pa[2] = pack_h2(sf[2*kt2+1][0], sf[2*kt2+1][1]);
            pa[3] = pack_h2(sf[2*kt2+1][2], sf[2*kt2+1][3]);
            #pragma unroll
            for (int nt = 0; nt < 16; nt += 2) {
                uint32_t b4[4];
                uint32_t addr = sVb + (uint32_t)((((kt2 * 16 + vRow) * SQ_STRIDE)
                                 + (nt + vSel) * 8) * 2);
                ldsm_x4_t(b4[0], b4[1], b4[2], b4[3], addr);
                mma16816(of[nt],     pa, b4);
                mma16816(of[nt + 1], pa, b4 + 2);
            }
        }

        // drain next-tile loads; protect write-after-read for stage reuse
        if (kt + 1 < ktiles) {
            cpa_wait0();
            __syncthreads();
        }
    }

    // ---- epilogue: normalize, write (B, L, H*DV) fp32 ----
    float inv0 = 1.f / l_r0;
    float inv1 = 1.f / l_r1;
    int row0 = n * CHUNK_ + m0 + warp * 16 + (lane >> 2);
    int colb = h * 128 + ((lane & 3) << 1);
    size_t ob0 = ((size_t)b * L_ + row0) * (size_t)(H_ * DV_);
    size_t ob1 = ob0 + (size_t)8 * (H_ * DV_);
    #pragma unroll
    for (int nt = 0; nt < 16; nt++) {
        int c = colb + nt * 8;
        *(float2*)(out + ob0 + c) = make_float2(of[nt][0] * inv0, of[nt][1] * inv0);
        *(float2*)(out + ob1 + c) = make_float2(of[nt][2] * inv1, of[nt][3] * inv1);
    }
}

// ---------------------------------------------------------------------------
extern "C" void kernel_launch(void* const* d_in, const int* in_sizes, int n_in,
                              void* d_out, int out_size) {
    const float* q = (const float*)d_in[0];
    const float* k = (const float*)d_in[1];
    const float* v = (const float*)d_in[2];
    float* out = (float*)d_out;

    const int smem_bytes = (128 + 4 * 64) * SQ_STRIDE * (int)sizeof(__half);
    cudaFuncSetAttribute(flash_kernel,
                         cudaFuncAttributeMaxDynamicSharedMemorySize, smem_bytes);

    rope_cvt_kernel<<<(B_ * L_ * H_) / 4, 256>>>(q, k, v);
    flash_kernel<<<dim3(8, H_, B_ * NC_), 256, smem_bytes>>>(out);
}

// round 3
// speedup vs baseline: 1.1678x; 1.0035x over previous
#include <cuda_runtime.h>
#include <cuda_fp16.h>
#include <cstdint>

#define B_ 4
#define L_ 4096
#define H_ 16
#define DH_ 128
#define DV_ 128
#define CHUNK_ 1024
#define NC_ (L_/CHUNK_)

// fp16 scratch, head-major [B][H][L][128]
__device__ __half g_q[(size_t)B_*H_*L_*DH_];
__device__ __half g_k[(size_t)B_*H_*L_*DH_];
__device__ __half g_v[(size_t)B_*H_*L_*DV_];

// ---------------------------------------------------------------------------
// Kernel 1: RoPE + scale-fold (1/sqrt(128) * log2e into Q) + fp32->fp16,
// relayout to head-major
// ---------------------------------------------------------------------------
__global__ void rope_cvt_kernel(const float* __restrict__ q,
                                const float* __restrict__ k,
                                const float* __restrict__ v) {
    int gid = blockIdx.x * 4 + (threadIdx.x >> 6);   // row in [0, B*L*H)
    int f   = threadIdx.x & 63;
    int h = gid % H_;
    int bt = gid / H_;
    int t = bt % L_;
    int b = bt / L_;

    size_t in_base  = (size_t)gid * 128;                       // (B,L,H,D)
    size_t out_base = (((size_t)(b*H_ + h))*L_ + t) * 128;     // (B,H,L,D)

    float inv = expf((float)f * (-9.210340371976184f / 64.0f));
    float ang = (float)t * inv;
    float s, c;
    sincosf(ang, &s, &c);

    // 1/sqrt(128) * log2(e): softmax done in base-2 domain downstream
    const float sc = 0.08838834764831845f * 1.4426950408889634f;

    float q1 = q[in_base + f], q2 = q[in_base + f + 64];
    float k1 = k[in_base + f], k2 = k[in_base + f + 64];

    g_q[out_base + f]      = __float2half_rn((q1*c - q2*s) * sc);
    g_q[out_base + f + 64] = __float2half_rn((q1*s + q2*c) * sc);
    g_k[out_base + f]      = __float2half_rn(k1*c - k2*s);
    g_k[out_base + f + 64] = __float2half_rn(k1*s + k2*c);
    g_v[out_base + f]      = __float2half_rn(v[in_base + f]);
    g_v[out_base + f + 64] = __float2half_rn(v[in_base + f + 64]);
}

// ---------------------------------------------------------------------------
// PTX helpers
// ---------------------------------------------------------------------------
__device__ __forceinline__ uint32_t smem_u32(const void* p) {
    return (uint32_t)__cvta_generic_to_shared(p);
}
__device__ __forceinline__ void ldsm_x4(uint32_t& a0, uint32_t& a1,
                                        uint32_t& a2, uint32_t& a3, uint32_t addr) {
    asm volatile("ldmatrix.sync.aligned.m8n8.x4.shared.b16 {%0,%1,%2,%3}, [%4];\n"
                 : "=r"(a0), "=r"(a1), "=r"(a2), "=r"(a3) : "r"(addr));
}
__device__ __forceinline__ void ldsm_x4_t(uint32_t& a0, uint32_t& a1,
                                          uint32_t& a2, uint32_t& a3, uint32_t addr) {
    asm volatile("ldmatrix.sync.aligned.m8n8.x4.trans.shared.b16 {%0,%1,%2,%3}, [%4];\n"
                 : "=r"(a0), "=r"(a1), "=r"(a2), "=r"(a3) : "r"(addr));
}
__device__ __forceinline__ void mma16816(float* d, const uint32_t* a, const uint32_t* b) {
    asm volatile(
        "mma.sync.aligned.m16n8k16.row.col.f32.f16.f16.f32 "
        "{%0,%1,%2,%3},{%4,%5,%6,%7},{%8,%9},{%0,%1,%2,%3};\n"
        : "+f"(d[0]), "+f"(d[1]), "+f"(d[2]), "+f"(d[3])
        : "r"(a[0]), "r"(a[1]), "r"(a[2]), "r"(a[3]), "r"(b[0]), "r"(b[1]));
}
__device__ __forceinline__ uint32_t pack_h2(float lo, float hi) {
    __half2 h = __floats2half2_rn(lo, hi);
    return *reinterpret_cast<uint32_t*>(&h);
}
__device__ __forceinline__ float fexp2(float x) {
    float r;
    asm("ex2.approx.f32 %0, %1;" : "=f"(r) : "f"(x));
    return r;
}
__device__ __forceinline__ void cpa16(uint32_t dst, const void* src) {
    asm volatile("cp.async.cg.shared.global [%0], [%1], 16;\n"
                 :: "r"(dst), "l"(src));
}
__device__ __forceinline__ void cpa_commit() {
    asm volatile("cp.async.commit_group;\n");
}
__device__ __forceinline__ void cpa_wait0() {
    asm volatile("cp.async.wait_group 0;\n");
}

// ---------------------------------------------------------------------------
// Kernel 2: flash attention in 1024-chunks, causal.
// CTA: 8 warps, BM=128 rows (16/warp), BN=64, 2-stage cp.async pipeline.
// ---------------------------------------------------------------------------
#define SQ_STRIDE 136   // 128 + 8 halves pad; 272B rows (16B-aligned, conflict-free)

__global__ __launch_bounds__(256, 1)
void flash_kernel(float* __restrict__ out) {
    extern __shared__ __half smem[];
    __half* Qs = smem;                          // 128 x 136
    __half* Ks = smem + 128 * SQ_STRIDE;        // 2 x (64 x 136)
    __half* Vs = Ks + 2 * 64 * SQ_STRIDE;       // 2 x (64 x 136)

    const int mtile = 7 - blockIdx.x;           // long CTAs first
    const int h     = blockIdx.y;
    const int bn    = blockIdx.z;
    const int b = bn / NC_, n = bn % NC_;
    const int m0 = mtile * 128;

    const int tid  = threadIdx.x;
    const int warp = tid >> 5;
    const int lane = tid & 31;

    const size_t headbase = ((size_t)(b*H_ + h)) * L_ * 128 + (size_t)n * CHUNK_ * 128;
    const __half* Kg = g_k + headbase;
    const __half* Vg = g_v + headbase;

    const uint32_t sQ = smem_u32(Qs);
    const uint32_t sK = smem_u32(Ks);
    const uint32_t sV = smem_u32(Vs);

    const int ktiles = 2 * mtile + 2;

    // ---- prologue: async-load Q tile + K/V tile 0 ----
    {
        const __half* Qg = g_q + headbase + (size_t)m0 * 128;
        #pragma unroll
        for (int i = tid; i < 128 * 16; i += 256) {
            int r = i >> 4, s = i & 15;
            cpa16(sQ + (uint32_t)((r * SQ_STRIDE + s * 8) * 2), Qg + r * 128 + s * 8);
        }
        #pragma unroll
        for (int i = tid; i < 64 * 16; i += 256) {
            int r = i >> 4, s = i & 15;
            uint32_t off = (uint32_t)((r * SQ_STRIDE + s * 8) * 2);
            cpa16(sK + off, Kg + r * 128 + s * 8);
            cpa16(sV + off, Vg + r * 128 + s * 8);
        }
        cpa_commit();
    }
    cpa_wait0();
    __syncthreads();

    // ---- Q fragments register-resident for whole K loop ----
    uint32_t qa[8][4];
    {
        int row = warp * 16 + (lane & 15);
        int col8 = (lane >> 4) << 3;
        #pragma unroll
        for (int kk = 0; kk < 8; kk++) {
            uint32_t addr = sQ + (uint32_t)((row * SQ_STRIDE + kk * 16 + col8) * 2);
            ldsm_x4(qa[kk][0], qa[kk][1], qa[kk][2], qa[kk][3], addr);
        }
    }

    // per-lane ldmatrix address parts
    const int kmat  = lane >> 3;                        // 0..3
    const int kRow  = ((kmat >> 1) << 3) + (lane & 7);  // row-within-(2x8)-pair
    const int kCol  = (kmat & 1) << 3;                  // 0 or 8
    const int vRow  = lane & 15;
    const int vSel  = lane >> 4;                        // 0/1 -> nt, nt+1

    // ---- online-softmax state ----
    float of[16][4];
    #pragma unroll
    for (int i = 0; i < 16; i++)
        #pragma unroll
        for (int j = 0; j < 4; j++) of[i][j] = 0.f;
    float m_r0 = -1e30f, m_r1 = -1e30f;
    float l_r0 = 0.f,    l_r1 = 0.f;

    for (int kt = 0; kt < ktiles; kt++) {
        const uint32_t sKb = sK + (uint32_t)((kt & 1) * 64 * SQ_STRIDE * 2);
        const uint32_t sVb = sV + (uint32_t)((kt & 1) * 64 * SQ_STRIDE * 2);

        // issue next tile's loads into the other buffer (overlaps with compute)
        if (kt + 1 < ktiles) {
            const __half* Kn = Kg + (size_t)(kt + 1) * 64 * 128;
            const __half* Vn = Vg + (size_t)(kt + 1) * 64 * 128;
            uint32_t sKn = sK + (uint32_t)(((kt + 1) & 1) * 64 * SQ_STRIDE * 2);
            uint32_t sVn = sV + (uint32_t)(((kt + 1) & 1) * 64 * SQ_STRIDE * 2);
            #pragma unroll
            for (int i = tid; i < 64 * 16; i += 256) {
                int r = i >> 4, s = i & 15;
                uint32_t off = (uint32_t)((r * SQ_STRIDE + s * 8) * 2);
                cpa16(sKn + off, Kn + r * 128 + s * 8);
                cpa16(sVn + off, Vn + r * 128 + s * 8);
            }
            cpa_commit();
        }

        // ---- S = Q K^T (16 x 64 per warp) ----
        float sf[8][4];
        #pragma unroll
        for (int i = 0; i < 8; i++)
            #pragma unroll
            for (int j = 0; j < 4; j++) sf[i][j] = 0.f;

        #pragma unroll
        for (int kk = 0; kk < 8; kk++) {
            #pragma unroll
            for (int nt = 0; nt < 8; nt += 2) {
                uint32_t b4[4];
                uint32_t addr = sKb + (uint32_t)((((nt * 8 + kRow) * SQ_STRIDE)
                                 + kk * 16 + kCol) * 2);
                ldsm_x4(b4[0], b4[1], b4[2], b4[3], addr);
                mma16816(sf[nt],     qa[kk], b4);
                mma16816(sf[nt + 1], qa[kk], b4 + 2);
            }
        }

        // ---- causal mask (diagonal-region tiles only) ----
        if (kt >= 2 * mtile) {
            int r0 = m0 + warp * 16 + (lane >> 2);
            int cbase = kt * 64 + ((lane & 3) << 1);
            #pragma unroll
            for (int nt = 0; nt < 8; nt++) {
                int c0 = cbase + nt * 8;
                if (c0     > r0)     sf[nt][0] = -1e30f;
                if (c0 + 1 > r0)     sf[nt][1] = -1e30f;
                if (c0     > r0 + 8) sf[nt][2] = -1e30f;
                if (c0 + 1 > r0 + 8) sf[nt][3] = -1e30f;
            }
        }

        // ---- online softmax (base-2 domain; log2e pre-folded into Q) ----
        float rmax0 = -1e30f, rmax1 = -1e30f;
        #pragma unroll
        for (int nt = 0; nt < 8; nt++) {
            rmax0 = fmaxf(rmax0, fmaxf(sf[nt][0], sf[nt][1]));
            rmax1 = fmaxf(rmax1, fmaxf(sf[nt][2], sf[nt][3]));
        }
        rmax0 = fmaxf(rmax0, __shfl_xor_sync(0xffffffffu, rmax0, 1));
        rmax0 = fmaxf(rmax0, __shfl_xor_sync(0xffffffffu, rmax0, 2));
        rmax1 = fmaxf(rmax1, __shfl_xor_sync(0xffffffffu, rmax1, 1));
        rmax1 = fmaxf(rmax1, __shfl_xor_sync(0xffffffffu, rmax1, 2));

        float nm0 = fmaxf(m_r0, rmax0);
        float nm1 = fmaxf(m_r1, rmax1);
        float sc0 = fexp2(m_r0 - nm0);
        float sc1 = fexp2(m_r1 - nm1);

        float rs0 = 0.f, rs1 = 0.f;
        #pragma unroll
        for (int nt = 0; nt < 8; nt++) {
            sf[nt][0] = fexp2(sf[nt][0] - nm0);
            sf[nt][1] = fexp2(sf[nt][1] - nm0);
            sf[nt][2] = fexp2(sf[nt][2] - nm1);
            sf[nt][3] = fexp2(sf[nt][3] - nm1);
            rs0 += sf[nt][0] + sf[nt][1];
            rs1 += sf[nt][2] + sf[nt][3];
        }
        rs0 += __shfl_xor_sync(0xffffffffu, rs0, 1);
        rs0 += __shfl_xor_sync(0xffffffffu, rs0, 2);
        rs1 += __shfl_xor_sync(0xffffffffu, rs1, 1);
        rs1 += __shfl_xor_sync(0xffffffffu, rs1, 2);

        l_r0 = l_r0 * sc0 + rs0;
        l_r1 = l_r1 * sc1 + rs1;
        m_r0 = nm0;
        m_r1 = nm1;

        #pragma unroll
        for (int nt = 0; nt < 16; nt++) {
            of[nt][0] *= sc0; of[nt][1] *= sc0;
            of[nt][2] *= sc1; of[nt][3] *= sc1;
        }

        // ---- O += P V ----
        #pragma unroll
        for (int kt2 = 0; kt2 < 4; kt2++) {
            uint32_t pa[4];
            pa[0] = pack_h2(sf[2*kt2][0],   sf[2*kt2][1]);
            pa[1] = pack_h2(sf[2*kt2][2],   sf[2*kt2][3]);
            pa[2] = pack_h2(sf[2*kt2+1][0], sf[2*kt2+1][1]);
            pa[3] = pack_h2(sf[2*kt2+1][2], sf[2*kt2+1][3]);
            #pragma unroll
            for (int nt = 0; nt < 16; nt += 2) {
                uint32_t b4[4];
                uint32_t addr = sVb + (uint32_t)((((kt2 * 16 + vRow) * SQ_STRIDE)
                                 + (nt + vSel) * 8) * 2);
                ldsm_x4_t(b4[0], b4[1], b4[2], b4[3], addr);
                mma16816(of[nt],     pa, b4);
                mma16816(of[nt + 1], pa, b4 + 2);
            }
        }

        // drain next-tile loads; protect write-after-read for stage reuse
        if (kt + 1 < ktiles) {
            cpa_wait0();
            __syncthreads();
        }
    }

    // ---- epilogue: normalize, write (B, L, H*DV) fp32 ----
    float inv0 = 1.f / l_r0;
    float inv1 = 1.f / l_r1;
    int row0 = n * CHUNK_ + m0 + warp * 16 + (lane >> 2);
    int colb = h * 128 + ((lane & 3) << 1);
    size_t ob0 = ((size_t)b * L_ + row0) * (size_t)(H_ * DV_);
    size_t ob1 = ob0 + (size_t)8 * (H_ * DV_);
    #pragma unroll
    for (int nt = 0; nt < 16; nt++) {
        int c = colb + nt * 8;
        *(float2*)(out + ob0 + c) = make_float2(of[nt][0] * inv0, of[nt][1] * inv0);
        *(float2*)(out + ob1 + c) = make_float2(of[nt][2] * inv1, of[nt][3] * inv1);
    }
}

// ---------------------------------------------------------------------------
extern "C" void kernel_launch(void* const* d_in, const int* in_sizes, int n_in,
                              void* d_out, int out_size) {
    const float* q = (const float*)d_in[0];
    const float* k = (const float*)d_in[1];
    const float* v = (const float*)d_in[2];
    float* out = (float*)d_out;

    const int smem_bytes = (128 + 4 * 64) * SQ_STRIDE * (int)sizeof(__half);
    cudaFuncSetAttribute(flash_kernel,
                         cudaFuncAttributeMaxDynamicSharedMemorySize, smem_bytes);

    rope_cvt_kernel<<<(B_ * L_ * H_) / 4, 256>>>(q, k, v);
    flash_kernel<<<dim3(8, H_, B_ * NC_), 256, smem_bytes>>>(out);
}